// round 9
// baseline (speedup 1.0000x reference)
#include <cuda_runtime.h>
#include <cuda_fp16.h>
#include <cstdint>

#define B_TOK 16384
#define N_CB  8192
#define DIM   512
#define MT    64           // tokens per CTA (2 CTAs/SM)
#define NTILE 128          // codes per n-tile
#define KCH   64           // k per chunk
#define KCHUNKS 8          // DIM/KCH
#define TILES (N_CB/NTILE) // 64
#define NTHREADS 256
#define NWARPS  8
#define MARGIN 0.25f
#define CAP   32

// ---- global scratch (no cudaMalloc allowed) ----
__device__ __align__(128) __half g_xh[B_TOK * DIM];
__device__ __align__(128) __half g_ch[N_CB * DIM];
__device__ __align__(128) float  g_c2[N_CB];

// ---- SMEM layout (bytes) ----
#define SM_C2   0          // 128 f32 = 512
#define SM_MAX  512        // 64 u32 -> 768
#define SM_CNT  768        // 64 u32 -> 1024
#define SM_IDX  1024       // 64 u32 -> 1280
#define SM_LST  1280       // 64*CAP u32 = 8192 -> 9472
#define SM_A    9472       // 8 chunks x [64 x 64] half = 65536 -> 75008
#define SM_B    75008      // 2 bufs x 16384 = 32768 -> 107776
#define SMEM_TOTAL 107776

// ---------------- helpers ----------------
__device__ __forceinline__ uint32_t smem_u32(const void* p) {
    uint32_t a;
    asm("{ .reg .u64 t; cvta.to.shared.u64 t, %1; cvt.u32.u64 %0, t; }" : "=r"(a) : "l"(p));
    return a;
}
__device__ __forceinline__ void cpa16(uint32_t dst, const void* src) {
    asm volatile("cp.async.cg.shared.global [%0], [%1], 16;" :: "r"(dst), "l"(src));
}
__device__ __forceinline__ void cpa_commit() { asm volatile("cp.async.commit_group;" ::: "memory"); }
__device__ __forceinline__ void cpa_wait0()  { asm volatile("cp.async.wait_group 0;"  ::: "memory"); }

__device__ __forceinline__ void ldsm4(uint32_t* r, uint32_t addr) {
    asm volatile("ldmatrix.sync.aligned.m8n8.x4.shared.b16 {%0,%1,%2,%3}, [%4];"
                 : "=r"(r[0]), "=r"(r[1]), "=r"(r[2]), "=r"(r[3]) : "r"(addr));
}
__device__ __forceinline__ void mma16816(float* d, const uint32_t* a, uint32_t b0, uint32_t b1) {
    asm volatile("mma.sync.aligned.m16n8k16.row.col.f32.f16.f16.f32 "
                 "{%0,%1,%2,%3}, {%4,%5,%6,%7}, {%8,%9}, {%0,%1,%2,%3};"
                 : "+f"(d[0]), "+f"(d[1]), "+f"(d[2]), "+f"(d[3])
                 : "r"(a[0]), "r"(a[1]), "r"(a[2]), "r"(a[3]), "r"(b0), "r"(b1));
}

__device__ __forceinline__ uint32_t sw128(uint32_t off) { return off ^ ((off >> 3) & 0x70); }

__device__ __forceinline__ uint32_t enc32(float s) {
    uint32_t u = __float_as_uint(s);
    return (u & 0x80000000u) ? ~u : (u | 0x80000000u);
}
__device__ __forceinline__ float dec32(uint32_t v) {
    return (v & 0x80000000u) ? __uint_as_float(v ^ 0x80000000u) : __uint_as_float(~v);
}
__device__ __forceinline__ unsigned long long pack_key(float t, unsigned n) {
    return ((unsigned long long)enc32(t) << 32) | (unsigned long long)(0xFFFFFFFFu - n);
}

// ---------------- pre-kernels ----------------
__global__ void c2_kernel(const float* __restrict__ cb) {
    int row  = blockIdx.x * blockDim.y + threadIdx.y;
    int lane = threadIdx.x;
    const float4* r = (const float4*)(cb + (size_t)row * DIM);
    float s = 0.f;
#pragma unroll
    for (int i = 0; i < 4; i++) {
        float4 v = r[lane + 32 * i];
        s += v.x*v.x + v.y*v.y + v.z*v.z + v.w*v.w;
    }
#pragma unroll
    for (int off = 16; off > 0; off >>= 1) s += __shfl_down_sync(0xFFFFFFFFu, s, off);
    if (lane == 0) g_c2[row] = s;
}

__global__ void tohalf_kernel(const float* __restrict__ src, __half* __restrict__ dst, int n4) {
    int i = blockIdx.x * blockDim.x + threadIdx.x;
    if (i >= n4) return;
    float4 v = ((const float4*)src)[i];
    ((__half2*)dst)[2*i]   = __floats2half2_rn(v.x, v.y);
    ((__half2*)dst)[2*i+1] = __floats2half2_rn(v.z, v.w);
}

// ---------------- main fused kernel ----------------
__global__ __launch_bounds__(NTHREADS, 2)
void vq_kernel(const float* __restrict__ x, const float* __restrict__ cb,
               const float* __restrict__ emb, float* __restrict__ out) {
    extern __shared__ char smem[];
    const uint32_t sb = smem_u32(smem);
    const int tid  = threadIdx.x;
    const int wid  = tid >> 5;
    const int lane = tid & 31;
    const int m0   = blockIdx.x * MT;
    const int wm   = wid & 1;       // m-group: rows wm*32 .. +31
    const int wn   = wid >> 1;      // n-group: cols wn*32 .. +31

    float*    c2s  = (float*)(smem + SM_C2);
    uint32_t* rmax = (uint32_t*)(smem + SM_MAX);
    uint32_t* cnt  = (uint32_t*)(smem + SM_CNT);
    uint32_t* idxs = (uint32_t*)(smem + SM_IDX);
    uint32_t* lst  = (uint32_t*)(smem + SM_LST);

    if (tid < MT) { rmax[tid] = 0u; cnt[tid] = 0u; }

    // ---- load A (x fp16) into SMEM: 8 chunks of [64 x 64] SW128 ----
    for (int i = tid; i < KCHUNKS * MT * 8; i += NTHREADS) {   // 16B units
        int ch = i >> 9, rem = i & 511, r = rem >> 3, u = rem & 7;
        cpa16(sb + SM_A + ch * 8192 + sw128(r * 128 + u * 16),
              g_xh + ((size_t)(m0 + r) * DIM + ch * KCH + u * 8));
    }
    cpa_commit();

    // per-thread ldmatrix address components (byte offsets inside a chunk)
    const int rowA[2] = { wm*32 + (lane & 15), wm*32 + 16 + (lane & 15) };
    const int kuA = (lane >> 4) * 16;                         // 0 or 16 bytes
    const int rowB = wn*32 + (lane & 7) + ((lane >> 4) << 3); // x4 covers 16 n-rows
    const int kuB = ((lane >> 3) & 1) * 16;

    float acc[2][4][4];

    for (int t = 0; t < TILES; t++) {
        // prefetch B chunk 0 ([128 x 64] half = 1024 16B units over 256 threads)
        {
            uint32_t dst = sb + SM_B;
            const __half* src = g_ch + (size_t)(t * NTILE) * DIM;
#pragma unroll
            for (int j = 0; j < 4; j++) {
                int i = tid * 4 + j, r = i >> 3, u = i & 7;
                cpa16(dst + sw128(r * 128 + u * 16), src + (size_t)r * DIM + u * 8);
            }
            cpa_commit();
        }
        if (tid < NTILE) c2s[tid] = g_c2[t * NTILE + tid];

#pragma unroll
        for (int mf = 0; mf < 2; mf++)
#pragma unroll
            for (int nf = 0; nf < 4; nf++)
#pragma unroll
                for (int k = 0; k < 4; k++) acc[mf][nf][k] = 0.f;

        for (int c = 0; c < KCHUNKS; c++) {
            cpa_wait0();
            __syncthreads();                     // chunk c visible to all
            if (c + 1 < KCHUNKS) {               // prefetch next chunk
                uint32_t dst = sb + SM_B + ((c + 1) & 1) * 16384;
                const __half* src = g_ch + (size_t)(t * NTILE) * DIM + (c + 1) * KCH;
#pragma unroll
                for (int j = 0; j < 4; j++) {
                    int i = tid * 4 + j, r = i >> 3, u = i & 7;
                    cpa16(dst + sw128(r * 128 + u * 16), src + (size_t)r * DIM + u * 8);
                }
                cpa_commit();
            }
            uint32_t abase = sb + SM_A + c * 8192;
            uint32_t bbase = sb + SM_B + (c & 1) * 16384;
#pragma unroll
            for (int ks = 0; ks < 4; ks++) {
                uint32_t a[2][4], b[2][4];
#pragma unroll
                for (int mf = 0; mf < 2; mf++)
                    ldsm4(a[mf], abase + sw128(rowA[mf] * 128 + ks * 32 + kuA));
#pragma unroll
                for (int g = 0; g < 2; g++)
                    ldsm4(b[g], bbase + sw128((rowB + g * 16) * 128 + ks * 32 + kuB));
#pragma unroll
                for (int mf = 0; mf < 2; mf++)
#pragma unroll
                    for (int nf = 0; nf < 4; nf++)
                        mma16816(acc[mf][nf], a[mf],
                                 b[nf >> 1][(nf & 1) * 2], b[nf >> 1][(nf & 1) * 2 + 1]);
            }
        }
        __syncthreads();                          // all MMAs done; c2s visible

        // ---- epilogue: running max ----
#pragma unroll
        for (int mf = 0; mf < 2; mf++)
#pragma unroll
            for (int rr = 0; rr < 2; rr++) {
                int row = wm*32 + mf*16 + (lane >> 2) + rr*8;
                float rb = -3.4e38f;
#pragma unroll
                for (int nf = 0; nf < 4; nf++)
#pragma unroll
                    for (int cc = 0; cc < 2; cc++) {
                        int col = wn*32 + nf*8 + (lane & 3)*2 + cc;
                        float s = fmaf(2.f, acc[mf][nf][rr*2 + cc], -c2s[col]);
                        if (s > rb) rb = s;
                    }
                atomicMax(&rmax[row], enc32(rb));
            }
        __syncthreads();

        // ---- admission: candidates within MARGIN of running max ----
#pragma unroll
        for (int mf = 0; mf < 2; mf++)
#pragma unroll
            for (int rr = 0; rr < 2; rr++) {
                int row = wm*32 + mf*16 + (lane >> 2) + rr*8;
                float thr = dec32(rmax[row]) - MARGIN;
#pragma unroll
                for (int nf = 0; nf < 4; nf++)
#pragma unroll
                    for (int cc = 0; cc < 2; cc++) {
                        int col = wn*32 + nf*8 + (lane & 3)*2 + cc;
                        float s = fmaf(2.f, acc[mf][nf][rr*2 + cc], -c2s[col]);
                        if (s >= thr) {
                            uint32_t slot = atomicAdd(&cnt[row], 1u);
                            if (slot < CAP) lst[row * CAP + slot] = (uint32_t)(t * NTILE + col);
                        }
                    }
            }
        __syncthreads();
    }

    // ---- phase 2: exact fp32 rescore of candidates ----
    for (int row = wid; row < MT; row += NWARPS) {
        unsigned n = cnt[row];
        unsigned long long bestk = 0ULL;
        const float* xr = x + (size_t)(m0 + row) * DIM;
        if (n == 0 || n > CAP) {
            for (int code = 0; code < N_CB; code++) {     // exact fallback (never on this data)
                const float* cr = cb + (size_t)code * DIM;
                float p = 0.f;
                for (int e = lane; e < DIM; e += 32) p = fmaf(xr[e], cr[e], p);
#pragma unroll
                for (int off = 16; off > 0; off >>= 1) p += __shfl_xor_sync(0xFFFFFFFFu, p, off);
                unsigned long long k = pack_key(fmaf(2.f, p, -g_c2[code]), (unsigned)code);
                if (k > bestk) bestk = k;
            }
        } else {
            for (unsigned j = 0; j < n; j++) {
                unsigned code = lst[row * CAP + j];
                const float* cr = cb + (size_t)code * DIM;
                float p = 0.f;
#pragma unroll
                for (int e = 0; e < DIM / 32; e++) p = fmaf(xr[lane + 32*e], cr[lane + 32*e], p);
#pragma unroll
                for (int off = 16; off > 0; off >>= 1) p += __shfl_xor_sync(0xFFFFFFFFu, p, off);
                unsigned long long k = pack_key(fmaf(2.f, p, -g_c2[code]), code);
                if (k > bestk) bestk = k;
            }
        }
        if (lane == 0) idxs[row] = 0xFFFFFFFFu - (uint32_t)(bestk & 0xFFFFFFFFu);
    }
    __syncthreads();

    // ---- gather: out[m] = embedding[idx[m]] ----
    const float4* e4 = (const float4*)emb;
    float4* o4 = (float4*)out;
    for (int i = tid; i < MT * (DIM / 4); i += NTHREADS) {
        int m = i >> 7, cc = i & 127;
        o4[(size_t)(m0 + m) * (DIM / 4) + cc] = e4[(size_t)idxs[m] * (DIM / 4) + cc];
    }
}

// ---------------------------------------------------------------------------
extern "C" void kernel_launch(void* const* d_in, const int* in_sizes, int n_in,
                              void* d_out, int out_size) {
    const float* x   = (const float*)d_in[0];
    const float* cb  = (const float*)d_in[1];
    const float* emb = (const float*)d_in[2];
    float* out = (float*)d_out;

    cudaFuncSetAttribute(vq_kernel, cudaFuncAttributeMaxDynamicSharedMemorySize, SMEM_TOTAL);

    __half *xh, *ch;
    cudaGetSymbolAddress((void**)&xh, g_xh);
    cudaGetSymbolAddress((void**)&ch, g_ch);

    tohalf_kernel<<<(B_TOK*DIM/4 + 255)/256, 256>>>(x,  xh, B_TOK*DIM/4);
    tohalf_kernel<<<(N_CB*DIM/4 + 255)/256, 256>>>(cb, ch, N_CB*DIM/4);
    c2_kernel<<<N_CB/8, dim3(32, 8)>>>(cb);
    vq_kernel<<<B_TOK/MT, NTHREADS, SMEM_TOTAL>>>(x, cb, emb, out);
}

// round 11
// speedup vs baseline: 1.2949x; 1.2949x over previous
#include <cuda_runtime.h>
#include <cuda_fp16.h>
#include <cstdint>

#define B_TOK 16384
#define N_CB  8192
#define DIM   512
#define MT    128          // tokens per CTA
#define NTILE 128          // codes per n-tile
#define KCH   64           // k per chunk
#define KCHUNKS 8          // DIM/KCH
#define TILES (N_CB/NTILE) // 64
#define NTHREADS 512
#define NWARPS  16
#define MARGIN 0.25f
#define CAP   32

// ---- global scratch (no cudaMalloc allowed) ----
__device__ __align__(128) __half g_xh[B_TOK * DIM];
__device__ __align__(128) __half g_ch[N_CB * DIM];
__device__ __align__(128) float  g_c2[N_CB];

// ---- SMEM layout (bytes) ----
#define SM_C2   0          // 128 f32
#define SM_MAX  512        // 128 u32 running max (encoded)
#define SM_CNT  1024       // 128 u32 candidate counts
#define SM_IDX  1536       // 128 u32 final indices
#define SM_LST  2048       // 128 * CAP u32 = 16384
#define SM_A    18432      // 8 chunks x [128 x 64] half (SW128) = 131072
#define SM_B    149504     // 2 bufs x 16384 = 32768
#define SMEM_TOTAL 182272

// ---------------- helpers ----------------
__device__ __forceinline__ uint32_t smem_u32(const void* p) {
    uint32_t a;
    asm("{ .reg .u64 t; cvta.to.shared.u64 t, %1; cvt.u32.u64 %0, t; }" : "=r"(a) : "l"(p));
    return a;
}
__device__ __forceinline__ void cpa16(uint32_t dst, const void* src) {
    asm volatile("cp.async.cg.shared.global [%0], [%1], 16;" :: "r"(dst), "l"(src));
}
__device__ __forceinline__ void cpa_commit() { asm volatile("cp.async.commit_group;" ::: "memory"); }
__device__ __forceinline__ void cpa_wait0()  { asm volatile("cp.async.wait_group 0;"  ::: "memory"); }

__device__ __forceinline__ void ldsm4(uint32_t* r, uint32_t addr) {
    asm volatile("ldmatrix.sync.aligned.m8n8.x4.shared.b16 {%0,%1,%2,%3}, [%4];"
                 : "=r"(r[0]), "=r"(r[1]), "=r"(r[2]), "=r"(r[3]) : "r"(addr));
}
__device__ __forceinline__ void mma16816(float* d, const uint32_t* a, uint32_t b0, uint32_t b1) {
    asm volatile("mma.sync.aligned.m16n8k16.row.col.f32.f16.f16.f32 "
                 "{%0,%1,%2,%3}, {%4,%5,%6,%7}, {%8,%9}, {%0,%1,%2,%3};"
                 : "+f"(d[0]), "+f"(d[1]), "+f"(d[2]), "+f"(d[3])
                 : "r"(a[0]), "r"(a[1]), "r"(a[2]), "r"(a[3]), "r"(b0), "r"(b1));
}

__device__ __forceinline__ uint32_t sw128(uint32_t off) { return off ^ ((off >> 3) & 0x70); }

__device__ __forceinline__ uint32_t enc32(float s) {
    uint32_t u = __float_as_uint(s);
    return (u & 0x80000000u) ? ~u : (u | 0x80000000u);
}
__device__ __forceinline__ float dec32(uint32_t v) {
    return (v & 0x80000000u) ? __uint_as_float(v ^ 0x80000000u) : __uint_as_float(~v);
}
__device__ __forceinline__ unsigned long long pack_key(float t, unsigned n) {
    return ((unsigned long long)enc32(t) << 32) | (unsigned long long)(0xFFFFFFFFu - n);
}

// ---------------- pre-kernels ----------------
__global__ void c2_kernel(const float* __restrict__ cb) {
    int row  = blockIdx.x * blockDim.y + threadIdx.y;
    int lane = threadIdx.x;
    const float4* r = (const float4*)(cb + (size_t)row * DIM);
    float s = 0.f;
#pragma unroll
    for (int i = 0; i < 4; i++) {
        float4 v = r[lane + 32 * i];
        s += v.x*v.x + v.y*v.y + v.z*v.z + v.w*v.w;
    }
#pragma unroll
    for (int off = 16; off > 0; off >>= 1) s += __shfl_down_sync(0xFFFFFFFFu, s, off);
    if (lane == 0) g_c2[row] = s;
}

__global__ void tohalf_kernel(const float* __restrict__ src, __half* __restrict__ dst, int n4) {
    int i = blockIdx.x * blockDim.x + threadIdx.x;
    if (i >= n4) return;
    float4 v = ((const float4*)src)[i];
    ((__half2*)dst)[2*i]   = __floats2half2_rn(v.x, v.y);
    ((__half2*)dst)[2*i+1] = __floats2half2_rn(v.z, v.w);
}

// ---------------- main fused kernel ----------------
__global__ __launch_bounds__(NTHREADS, 1)
void vq_kernel(const float* __restrict__ x, const float* __restrict__ cb,
               const float* __restrict__ emb, float* __restrict__ out) {
    extern __shared__ char smem[];
    const uint32_t sb = smem_u32(smem);
    const int tid  = threadIdx.x;
    const int wid  = tid >> 5;
    const int lane = tid & 31;
    const int m0   = blockIdx.x * MT;
    const int wm   = wid & 3;       // m-group: rows wm*32 .. +31
    const int wn   = wid >> 2;      // n-group: cols wn*32 .. +31

    float*    c2s  = (float*)(smem + SM_C2);
    uint32_t* rmax = (uint32_t*)(smem + SM_MAX);
    uint32_t* cnt  = (uint32_t*)(smem + SM_CNT);
    uint32_t* idxs = (uint32_t*)(smem + SM_IDX);
    uint32_t* lst  = (uint32_t*)(smem + SM_LST);

    if (tid < MT) { rmax[tid] = 0u; cnt[tid] = 0u; }

    // ---- load A (x fp16) into SMEM: 8 chunks of [128 x 64] SW128 ----
    for (int i = tid; i < KCHUNKS * MT * 8; i += NTHREADS) {   // 16B units
        int ch = i >> 10, rem = i & 1023, r = rem >> 3, u = rem & 7;
        cpa16(sb + SM_A + ch * 16384 + sw128(r * 128 + u * 16),
              g_xh + ((size_t)(m0 + r) * DIM + ch * KCH + u * 8));
    }
    cpa_commit();

    // per-thread ldmatrix address components (byte offsets inside a chunk)
    const int rowA[2] = { wm*32 + (lane & 15), wm*32 + 16 + (lane & 15) };
    const int kuA = (lane >> 4) * 16;                         // 0 or 16 bytes
    const int rowB = wn*32 + (lane & 7) + ((lane >> 4) << 3); // x4 covers 16 n-rows
    const int kuB = ((lane >> 3) & 1) * 16;

    float acc[2][4][4];

    for (int t = 0; t < TILES; t++) {
        // prefetch B chunk 0 (1024 16B units over 512 threads)
        {
            uint32_t dst = sb + SM_B;
            const __half* src = g_ch + (size_t)(t * NTILE) * DIM;
#pragma unroll
            for (int j = 0; j < 2; j++) {
                int i = tid * 2 + j, r = i >> 3, u = i & 7;
                cpa16(dst + sw128(r * 128 + u * 16), src + (size_t)r * DIM + u * 8);
            }
            cpa_commit();
        }
        if (tid < NTILE) c2s[tid] = g_c2[t * NTILE + tid];

#pragma unroll
        for (int mf = 0; mf < 2; mf++)
#pragma unroll
            for (int nf = 0; nf < 4; nf++)
#pragma unroll
                for (int k = 0; k < 4; k++) acc[mf][nf][k] = 0.f;

        for (int c = 0; c < KCHUNKS; c++) {
            cpa_wait0();
            __syncthreads();                     // chunk c visible to all
            if (c + 1 < KCHUNKS) {               // prefetch next chunk
                uint32_t dst = sb + SM_B + ((c + 1) & 1) * 16384;
                const __half* src = g_ch + (size_t)(t * NTILE) * DIM + (c + 1) * KCH;
#pragma unroll
                for (int j = 0; j < 2; j++) {
                    int i = tid * 2 + j, r = i >> 3, u = i & 7;
                    cpa16(dst + sw128(r * 128 + u * 16), src + (size_t)r * DIM + u * 8);
                }
                cpa_commit();
            }
            const uint32_t abase = sb + SM_A + c * 16384;
            const uint32_t bbase = sb + SM_B + (c & 1) * 16384;

            // ---- software-pipelined fragments: load ks+1 while MMA'ing ks ----
            uint32_t afr[2][2][4], bfr[2][2][4];
#pragma unroll
            for (int mf = 0; mf < 2; mf++)
                ldsm4(afr[0][mf], abase + sw128(rowA[mf] * 128 + kuA));
#pragma unroll
            for (int gg = 0; gg < 2; gg++)
                ldsm4(bfr[0][gg], bbase + sw128((rowB + gg * 16) * 128 + kuB));
#pragma unroll
            for (int ks = 0; ks < 4; ks++) {
                const int cur = ks & 1, nxt = cur ^ 1;
                if (ks < 3) {
#pragma unroll
                    for (int mf = 0; mf < 2; mf++)
                        ldsm4(afr[nxt][mf], abase + sw128(rowA[mf] * 128 + (ks+1) * 32 + kuA));
#pragma unroll
                    for (int gg = 0; gg < 2; gg++)
                        ldsm4(bfr[nxt][gg], bbase + sw128((rowB + gg * 16) * 128 + (ks+1) * 32 + kuB));
                }
#pragma unroll
                for (int mf = 0; mf < 2; mf++)
#pragma unroll
                    for (int nf = 0; nf < 4; nf++)
                        mma16816(acc[mf][nf], afr[cur][mf],
                                 bfr[cur][nf >> 1][(nf & 1) * 2], bfr[cur][nf >> 1][(nf & 1) * 2 + 1]);
            }
        }
        __syncthreads();                          // all MMAs done; c2s visible

        // ---- epilogue: running max ----
#pragma unroll
        for (int mf = 0; mf < 2; mf++)
#pragma unroll
            for (int rr = 0; rr < 2; rr++) {
                int row = wm*32 + mf*16 + (lane >> 2) + rr*8;
                float rb = -3.4e38f;
#pragma unroll
                for (int nf = 0; nf < 4; nf++)
#pragma unroll
                    for (int cc = 0; cc < 2; cc++) {
                        int col = wn*32 + nf*8 + (lane & 3)*2 + cc;
                        float s = fmaf(2.f, acc[mf][nf][rr*2 + cc], -c2s[col]);
                        if (s > rb) rb = s;
                    }
                atomicMax(&rmax[row], enc32(rb));
            }
        __syncthreads();

        // ---- admission: candidates within MARGIN of running max ----
#pragma unroll
        for (int mf = 0; mf < 2; mf++)
#pragma unroll
            for (int rr = 0; rr < 2; rr++) {
                int row = wm*32 + mf*16 + (lane >> 2) + rr*8;
                float thr = dec32(rmax[row]) - MARGIN;
#pragma unroll
                for (int nf = 0; nf < 4; nf++)
#pragma unroll
                    for (int cc = 0; cc < 2; cc++) {
                        int col = wn*32 + nf*8 + (lane & 3)*2 + cc;
                        float s = fmaf(2.f, acc[mf][nf][rr*2 + cc], -c2s[col]);
                        if (s >= thr) {
                            uint32_t slot = atomicAdd(&cnt[row], 1u);
                            if (slot < CAP) lst[row * CAP + slot] = (uint32_t)(t * NTILE + col);
                        }
                    }
            }
        __syncthreads();
    }

    // ---- phase 2: exact fp32 rescore of candidates ----
    for (int row = wid; row < MT; row += NWARPS) {
        unsigned n = cnt[row];
        unsigned long long bestk = 0ULL;
        const float* xr = x + (size_t)(m0 + row) * DIM;
        if (n == 0 || n > CAP) {
            for (int code = 0; code < N_CB; code++) {     // exact fallback (never on this data)
                const float* cr = cb + (size_t)code * DIM;
                float p = 0.f;
                for (int e = lane; e < DIM; e += 32) p = fmaf(xr[e], cr[e], p);
#pragma unroll
                for (int off = 16; off > 0; off >>= 1) p += __shfl_xor_sync(0xFFFFFFFFu, p, off);
                unsigned long long k = pack_key(fmaf(2.f, p, -g_c2[code]), (unsigned)code);
                if (k > bestk) bestk = k;
            }
        } else {
            for (unsigned j = 0; j < n; j++) {
                unsigned code = lst[row * CAP + j];
                const float* cr = cb + (size_t)code * DIM;
                float p = 0.f;
#pragma unroll
                for (int e = 0; e < DIM / 32; e++) p = fmaf(xr[lane + 32*e], cr[lane + 32*e], p);
#pragma unroll
                for (int off = 16; off > 0; off >>= 1) p += __shfl_xor_sync(0xFFFFFFFFu, p, off);
                unsigned long long k = pack_key(fmaf(2.f, p, -g_c2[code]), code);
                if (k > bestk) bestk = k;
            }
        }
        if (lane == 0) idxs[row] = 0xFFFFFFFFu - (uint32_t)(bestk & 0xFFFFFFFFu);
    }
    __syncthreads();

    // ---- gather: out[m] = embedding[idx[m]] ----
    const float4* e4 = (const float4*)emb;
    float4* o4 = (float4*)out;
    for (int i = tid; i < MT * (DIM / 4); i += NTHREADS) {
        int m = i >> 7, cc = i & 127;
        o4[(size_t)(m0 + m) * (DIM / 4) + cc] = e4[(size_t)idxs[m] * (DIM / 4) + cc];
    }
}

// ---------------------------------------------------------------------------
extern "C" void kernel_launch(void* const* d_in, const int* in_sizes, int n_in,
                              void* d_out, int out_size) {
    const float* x   = (const float*)d_in[0];
    const float* cb  = (const float*)d_in[1];
    const float* emb = (const float*)d_in[2];
    float* out = (float*)d_out;

    cudaFuncSetAttribute(vq_kernel, cudaFuncAttributeMaxDynamicSharedMemorySize, SMEM_TOTAL);

    __half *xh, *ch;
    cudaGetSymbolAddress((void**)&xh, g_xh);
    cudaGetSymbolAddress((void**)&ch, g_ch);

    tohalf_kernel<<<(B_TOK*DIM/4 + 255)/256, 256>>>(x,  xh, B_TOK*DIM/4);
    tohalf_kernel<<<(N_CB*DIM/4 + 255)/256, 256>>>(cb, ch, N_CB*DIM/4);
    c2_kernel<<<N_CB/8, dim3(32, 8)>>>(cb);
    vq_kernel<<<B_TOK/MT, NTHREADS, SMEM_TOTAL>>>(x, cb, emb, out);
}

// round 14
// speedup vs baseline: 1.3035x; 1.0066x over previous
#include <cuda_runtime.h>
#include <cuda_fp16.h>
#include <cstdint>

#define B_TOK 16384
#define N_CB  8192
#define DIM   512
#define MT    128          // tokens per CTA
#define NTILE 128          // codes per n-tile
#define KCH   64           // k per chunk
#define KCHUNKS 8          // DIM/KCH
#define TILES (N_CB/NTILE) // 64
#define NTHREADS 512
#define NWARPS  16
#define MARGIN 0.25f
#define CAP   32

// ---- global scratch (no cudaMalloc allowed) ----
__device__ __align__(128) __half g_xh[B_TOK * DIM];
__device__ __align__(128) __half g_ch[N_CB * DIM];
__device__ __align__(128) float  g_c2[N_CB];

// ---- SMEM layout (bytes) ----
#define SM_C2   0          // 128 f32
#define SM_MAX  512        // 128 u32 running max (encoded)
#define SM_CNT  1024       // 128 u32 candidate counts
#define SM_IDX  1536       // 128 u32 final indices
#define SM_LST  2048       // 128 * CAP u32 = 16384
#define SM_A    18432      // 8 chunks x [128 x 64] half (SW128) = 131072
#define SM_B    149504     // 2 bufs x 16384 = 32768
#define SMEM_TOTAL 182272

// ---------------- helpers ----------------
__device__ __forceinline__ uint32_t smem_u32(const void* p) {
    uint32_t a;
    asm("{ .reg .u64 t; cvta.to.shared.u64 t, %1; cvt.u32.u64 %0, t; }" : "=r"(a) : "l"(p));
    return a;
}
__device__ __forceinline__ void cpa16(uint32_t dst, const void* src) {
    asm volatile("cp.async.cg.shared.global [%0], [%1], 16;" :: "r"(dst), "l"(src));
}
__device__ __forceinline__ void cpa_commit() { asm volatile("cp.async.commit_group;" ::: "memory"); }
__device__ __forceinline__ void cpa_wait0()  { asm volatile("cp.async.wait_group 0;"  ::: "memory"); }

__device__ __forceinline__ void ldsm4(uint32_t* r, uint32_t addr) {
    asm volatile("ldmatrix.sync.aligned.m8n8.x4.shared.b16 {%0,%1,%2,%3}, [%4];"
                 : "=r"(r[0]), "=r"(r[1]), "=r"(r[2]), "=r"(r[3]) : "r"(addr));
}
__device__ __forceinline__ void mma16816(float* d, const uint32_t* a, uint32_t b0, uint32_t b1) {
    asm volatile("mma.sync.aligned.m16n8k16.row.col.f32.f16.f16.f32 "
                 "{%0,%1,%2,%3}, {%4,%5,%6,%7}, {%8,%9}, {%0,%1,%2,%3};"
                 : "+f"(d[0]), "+f"(d[1]), "+f"(d[2]), "+f"(d[3])
                 : "r"(a[0]), "r"(a[1]), "r"(a[2]), "r"(a[3]), "r"(b0), "r"(b1));
}

__device__ __forceinline__ uint32_t sw128(uint32_t off) { return off ^ ((off >> 3) & 0x70); }

__device__ __forceinline__ uint32_t enc32(float s) {
    uint32_t u = __float_as_uint(s);
    return (u & 0x80000000u) ? ~u : (u | 0x80000000u);
}
__device__ __forceinline__ float dec32(uint32_t v) {
    return (v & 0x80000000u) ? __uint_as_float(v ^ 0x80000000u) : __uint_as_float(~v);
}
__device__ __forceinline__ unsigned long long pack_key(float t, unsigned n) {
    return ((unsigned long long)enc32(t) << 32) | (unsigned long long)(0xFFFFFFFFu - n);
}

// ---------------- pre-kernels ----------------
__global__ void c2_kernel(const float* __restrict__ cb) {
    int row  = blockIdx.x * blockDim.y + threadIdx.y;
    int lane = threadIdx.x;
    const float4* r = (const float4*)(cb + (size_t)row * DIM);
    float s = 0.f;
#pragma unroll
    for (int i = 0; i < 4; i++) {
        float4 v = r[lane + 32 * i];
        s += v.x*v.x + v.y*v.y + v.z*v.z + v.w*v.w;
    }
#pragma unroll
    for (int off = 16; off > 0; off >>= 1) s += __shfl_down_sync(0xFFFFFFFFu, s, off);
    if (lane == 0) g_c2[row] = s;
}

__global__ void tohalf_kernel(const float* __restrict__ src, __half* __restrict__ dst, int n4) {
    int i = blockIdx.x * blockDim.x + threadIdx.x;
    if (i >= n4) return;
    float4 v = ((const float4*)src)[i];
    ((__half2*)dst)[2*i]   = __floats2half2_rn(v.x, v.y);
    ((__half2*)dst)[2*i+1] = __floats2half2_rn(v.z, v.w);
}

// ---------------- main fused kernel ----------------
__global__ __launch_bounds__(NTHREADS, 1)
void vq_kernel(const float* __restrict__ x, const float* __restrict__ cb,
               const float* __restrict__ emb, float* __restrict__ out) {
    extern __shared__ char smem[];
    const uint32_t sb = smem_u32(smem);
    const int tid  = threadIdx.x;
    const int wid  = tid >> 5;
    const int lane = tid & 31;
    const int m0   = blockIdx.x * MT;
    const int wm   = wid & 3;            // m-group: rows wm*32 .. +31
    const int wn   = wid >> 2;           // n-group: cols wn*32 .. +31
    const int krot = (wid * 37) & 3;     // per-warp ks rotation (phase stagger)

    float*    c2s  = (float*)(smem + SM_C2);
    uint32_t* rmax = (uint32_t*)(smem + SM_MAX);
    uint32_t* cnt  = (uint32_t*)(smem + SM_CNT);
    uint32_t* idxs = (uint32_t*)(smem + SM_IDX);
    uint32_t* lst  = (uint32_t*)(smem + SM_LST);

    if (tid < MT) { rmax[tid] = 0u; cnt[tid] = 0u; }

    // ---- load A (x fp16) into SMEM: 8 chunks of [128 x 64] SW128 ----
    for (int i = tid; i < KCHUNKS * MT * 8; i += NTHREADS) {   // 16B units
        int ch = i >> 10, rem = i & 1023, r = rem >> 3, u = rem & 7;
        cpa16(sb + SM_A + ch * 16384 + sw128(r * 128 + u * 16),
              g_xh + ((size_t)(m0 + r) * DIM + ch * KCH + u * 8));
    }
    cpa_commit();

    // per-thread ldmatrix address components (byte offsets inside a chunk)
    const int rowA[2] = { wm*32 + (lane & 15), wm*32 + 16 + (lane & 15) };
    const int kuA = (lane >> 4) * 16;                         // 0 or 16 bytes
    const int rowB = wn*32 + (lane & 7) + ((lane >> 4) << 3); // x4 covers 16 n-rows
    const int kuB = ((lane >> 3) & 1) * 16;

    float acc[2][4][4];

    for (int t = 0; t < TILES; t++) {
        // prefetch B chunk 0 (1024 16B units over 512 threads)
        {
            uint32_t dst = sb + SM_B;
            const __half* src = g_ch + (size_t)(t * NTILE) * DIM;
#pragma unroll
            for (int j = 0; j < 2; j++) {
                int i = tid * 2 + j, r = i >> 3, u = i & 7;
                cpa16(dst + sw128(r * 128 + u * 16), src + (size_t)r * DIM + u * 8);
            }
            cpa_commit();
        }
        if (tid < NTILE) c2s[tid] = g_c2[t * NTILE + tid];

#pragma unroll
        for (int mf = 0; mf < 2; mf++)
#pragma unroll
            for (int nf = 0; nf < 4; nf++)
#pragma unroll
                for (int k = 0; k < 4; k++) acc[mf][nf][k] = 0.f;

        for (int c = 0; c < KCHUNKS; c++) {
            cpa_wait0();
            __syncthreads();                     // chunk c visible to all
            if (c + 1 < KCHUNKS) {               // prefetch next chunk
                uint32_t dst = sb + SM_B + ((c + 1) & 1) * 16384;
                const __half* src = g_ch + (size_t)(t * NTILE) * DIM + (c + 1) * KCH;
#pragma unroll
                for (int j = 0; j < 2; j++) {
                    int i = tid * 2 + j, r = i >> 3, u = i & 7;
                    cpa16(dst + sw128(r * 128 + u * 16), src + (size_t)r * DIM + u * 8);
                }
                cpa_commit();
            }
            uint32_t abase = sb + SM_A + c * 16384;
            uint32_t bbase = sb + SM_B + (c & 1) * 16384;
            // per-warp rotated ks order de-phases LDSM bursts vs MMA bursts
#pragma unroll
            for (int ks = 0; ks < 4; ks++) {
                const int ko = ((ks + krot) & 3) * 32;        // byte offset for this step
                uint32_t a[2][4], b[2][4];
#pragma unroll
                for (int mf = 0; mf < 2; mf++)
                    ldsm4(a[mf], abase + sw128(rowA[mf] * 128 + ko + kuA));
#pragma unroll
                for (int g = 0; g < 2; g++)
                    ldsm4(b[g], bbase + sw128((rowB + g * 16) * 128 + ko + kuB));
#pragma unroll
                for (int mf = 0; mf < 2; mf++)
#pragma unroll
                    for (int nf = 0; nf < 4; nf++)
                        mma16816(acc[mf][nf], a[mf],
                                 b[nf >> 1][(nf & 1) * 2], b[nf >> 1][(nf & 1) * 2 + 1]);
            }
        }
        __syncthreads();                          // all MMAs done; c2s visible

        // ---- epilogue: running max ----
#pragma unroll
        for (int mf = 0; mf < 2; mf++)
#pragma unroll
            for (int rr = 0; rr < 2; rr++) {
                int row = wm*32 + mf*16 + (lane >> 2) + rr*8;
                float rb = -3.4e38f;
#pragma unroll
                for (int nf = 0; nf < 4; nf++)
#pragma unroll
                    for (int cc = 0; cc < 2; cc++) {
                        int col = wn*32 + nf*8 + (lane & 3)*2 + cc;
                        float s = fmaf(2.f, acc[mf][nf][rr*2 + cc], -c2s[col]);
                        if (s > rb) rb = s;
                    }
                atomicMax(&rmax[row], enc32(rb));
            }
        __syncthreads();

        // ---- admission: candidates within MARGIN of running max ----
#pragma unroll
        for (int mf = 0; mf < 2; mf++)
#pragma unroll
            for (int rr = 0; rr < 2; rr++) {
                int row = wm*32 + mf*16 + (lane >> 2) + rr*8;
                float thr = dec32(rmax[row]) - MARGIN;
#pragma unroll
                for (int nf = 0; nf < 4; nf++)
#pragma unroll
                    for (int cc = 0; cc < 2; cc++) {
                        int col = wn*32 + nf*8 + (lane & 3)*2 + cc;
                        float s = fmaf(2.f, acc[mf][nf][rr*2 + cc], -c2s[col]);
                        if (s >= thr) {
                            uint32_t slot = atomicAdd(&cnt[row], 1u);
                            if (slot < CAP) lst[row * CAP + slot] = (uint32_t)(t * NTILE + col);
                        }
                    }
            }
        __syncthreads();
    }

    // ---- phase 2: exact fp32 rescore of candidates ----
    for (int row = wid; row < MT; row += NWARPS) {
        unsigned n = cnt[row];
        unsigned long long bestk = 0ULL;
        const float* xr = x + (size_t)(m0 + row) * DIM;
        if (n == 0 || n > CAP) {
            for (int code = 0; code < N_CB; code++) {     // exact fallback (never on this data)
                const float* cr = cb + (size_t)code * DIM;
                float p = 0.f;
                for (int e = lane; e < DIM; e += 32) p = fmaf(xr[e], cr[e], p);
#pragma unroll
                for (int off = 16; off > 0; off >>= 1) p += __shfl_xor_sync(0xFFFFFFFFu, p, off);
                unsigned long long k = pack_key(fmaf(2.f, p, -g_c2[code]), (unsigned)code);
                if (k > bestk) bestk = k;
            }
        } else {
            for (unsigned j = 0; j < n; j++) {
                unsigned code = lst[row * CAP + j];
                const float* cr = cb + (size_t)code * DIM;
                float p = 0.f;
#pragma unroll
                for (int e = 0; e < DIM / 32; e++) p = fmaf(xr[lane + 32*e], cr[lane + 32*e], p);
#pragma unroll
                for (int off = 16; off > 0; off >>= 1) p += __shfl_xor_sync(0xFFFFFFFFu, p, off);
                unsigned long long k = pack_key(fmaf(2.f, p, -g_c2[code]), code);
                if (k > bestk) bestk = k;
            }
        }
        if (lane == 0) idxs[row] = 0xFFFFFFFFu - (uint32_t)(bestk & 0xFFFFFFFFu);
    }
    __syncthreads();

    // ---- gather: out[m] = embedding[idx[m]] ----
    const float4* e4 = (const float4*)emb;
    float4* o4 = (float4*)out;
    for (int i = tid; i < MT * (DIM / 4); i += NTHREADS) {
        int m = i >> 7, cc = i & 127;
        o4[(size_t)(m0 + m) * (DIM / 4) + cc] = e4[(size_t)idxs[m] * (DIM / 4) + cc];
    }
}

// ---------------------------------------------------------------------------
extern "C" void kernel_launch(void* const* d_in, const int* in_sizes, int n_in,
                              void* d_out, int out_size) {
    const float* x   = (const float*)d_in[0];
    const float* cb  = (const float*)d_in[1];
    const float* emb = (const float*)d_in[2];
    float* out = (float*)d_out;

    cudaFuncSetAttribute(vq_kernel, cudaFuncAttributeMaxDynamicSharedMemorySize, SMEM_TOTAL);

    __half *xh, *ch;
    cudaGetSymbolAddress((void**)&xh, g_xh);
    cudaGetSymbolAddress((void**)&ch, g_ch);

    tohalf_kernel<<<(B_TOK*DIM/4 + 255)/256, 256>>>(x,  xh, B_TOK*DIM/4);
    tohalf_kernel<<<(N_CB*DIM/4 + 255)/256, 256>>>(cb, ch, N_CB*DIM/4);
    c2_kernel<<<N_CB/8, dim3(32, 8)>>>(cb);
    vq_kernel<<<B_TOK/MT, NTHREADS, SMEM_TOTAL>>>(x, cb, emb, out);
}